// round 14
// baseline (speedup 1.0000x reference)
#include <cuda_runtime.h>
#include <cuda_fp16.h>
#include <cstdint>

#define NN 2048
#define DD 512
#define KPC 8
#define TM 128
#define TN 64
#define KS 64
#define NSLAB (DD / KS)
#define NGEMM 272          // symmetric 128x64 tiles, tj >= 2*ti

// ---------------- scratch (no allocations allowed) ----------------
__device__ __half g_xf[NN * DD];             // fp16 normalized (MMA operand)
__device__ float g_sq[NN];
__device__ float g_dist[(size_t)NN * NN];    // 16 MB distance matrix
__device__ float g_row[NN * 4];              // cnt, trip_sum, pos_sum, neg_sum
__device__ int g_done;

// ---------------- helpers ----------------
__device__ __forceinline__ uint32_t smem_to_u32(const void* p) {
    uint32_t a;
    asm("{ .reg .u64 t; cvta.to.shared.u64 t, %1; cvt.u32.u64 %0, t; }" : "=r"(a) : "l"(p));
    return a;
}
__device__ __forceinline__ float fast_exp2(float x) { float y; asm("ex2.approx.f32 %0, %1;" : "=f"(y) : "f"(x)); return y; }
__device__ __forceinline__ float fast_log2(float x) { float y; asm("lg2.approx.f32 %0, %1;" : "=f"(y) : "f"(x)); return y; }
__device__ __forceinline__ float warp_sum(float v) {
    #pragma unroll
    for (int o = 16; o; o >>= 1) v += __shfl_xor_sync(0xffffffffu, v, o);
    return v;
}

#define CPA(dst, src) \
    asm volatile("cp.async.cg.shared.global [%0], [%1], 16;" :: "r"(dst), "l"(src))
#define CPA_COMMIT() asm volatile("cp.async.commit_group;" ::: "memory")

__device__ __forceinline__ void ldm_x4(uint32_t* r, uint32_t addr) {
    asm volatile("ldmatrix.sync.aligned.m8n8.x4.shared.b16 {%0,%1,%2,%3}, [%4];"
                 : "=r"(r[0]), "=r"(r[1]), "=r"(r[2]), "=r"(r[3]) : "r"(addr));
}
__device__ __forceinline__ void mma_fp16(float* c, const uint32_t* a, uint32_t b0, uint32_t b1) {
    asm volatile(
        "mma.sync.aligned.m16n8k16.row.col.f32.f16.f16.f32 "
        "{%0,%1,%2,%3}, {%4,%5,%6,%7}, {%8,%9}, {%0,%1,%2,%3};"
        : "+f"(c[0]), "+f"(c[1]), "+f"(c[2]), "+f"(c[3])
        : "r"(a[0]), "r"(a[1]), "r"(a[2]), "r"(a[3]), "r"(b0), "r"(b1));
}

// ---------------------------------------------------------------------------
// 1) prep: normalize + fp16 + sq only (positives come from g_dist later)
// ---------------------------------------------------------------------------
__global__ __launch_bounds__(256) void prep_kernel(const float* __restrict__ in) {
    const int tid = threadIdx.x;
    const int w = tid >> 5;
    const int l = tid & 31;
    const int row = blockIdx.x * 8 + w;
    if (blockIdx.x == 0 && tid == 0) g_done = 0;

    float4 v[4];
    const float4* src = reinterpret_cast<const float4*>(in + row * DD) + l * 4;
    #pragma unroll
    for (int q = 0; q < 4; q++) v[q] = src[q];
    float ss = 0.0f;
    #pragma unroll
    for (int q = 0; q < 4; q++)
        ss += v[q].x * v[q].x + v[q].y * v[q].y + v[q].z * v[q].z + v[q].w * v[q].w;
    ss = warp_sum(ss);
    float s = 4.0f * rsqrtf(ss);

    __half2* pf = reinterpret_cast<__half2*>(g_xf + row * DD + l * 16);
    #pragma unroll
    for (int q = 0; q < 4; q++) {
        pf[q * 2 + 0] = __half2(__float2half_rn(v[q].x * s), __float2half_rn(v[q].y * s));
        pf[q * 2 + 1] = __half2(__float2half_rn(v[q].z * s), __float2half_rn(v[q].w * s));
    }
    if (l == 0) g_sq[row] = ss * s * s;
}

// ---------------------------------------------------------------------------
// 2) gemm_kernel: symmetric HMMA Gram, 272 tiles of 128x64, 2 CTAs/SM.
//    Band tiles (tj in {2ti, 2ti+1}) store normally (they self-cover mirrors);
//    off-band tiles store normal + transposed (smem-staged).
// ---------------------------------------------------------------------------
#define SM_SQI 0
#define SM_SQJ 512
#define SM_BUF 1024
#define A_OFF 0
#define B_OFF 16384
#define BUFSZ 24576
#define TSTRIDE 132
#define SMEM_TOTAL (SM_BUF + 2 * BUFSZ)       // 50176; transpose buf (64*132*4=33792) reuses it

__device__ __forceinline__ void load_slab_async(uint32_t smb, int buf, int s,
                                                int bi, int bj, int tid) {
    const int k0 = s * KS;
    const uint32_t bufb = smb + SM_BUF + buf * BUFSZ;
    // A: 128 rows x 8 chunks of 16B; 2 threads per row
    {
        const int row = tid >> 1;
        const int cb = (tid & 1) * 4;
        const char* sp = reinterpret_cast<const char*>(g_xf + (bi + row) * DD + k0);
        uint32_t dA = bufb + A_OFF + row * 128;
        #pragma unroll
        for (int c = 0; c < 4; c++) {
            int ch = cb + c;
            CPA(dA + (((ch ^ (row & 7))) << 4), sp + ch * 16);
        }
    }
    // B: 64 rows x 8 chunks; 4 threads per row
    {
        const int row = tid >> 2;
        const int cb = (tid & 3) * 2;
        const char* sp = reinterpret_cast<const char*>(g_xf + (bj + row) * DD + k0);
        uint32_t dB = bufb + B_OFF + row * 128;
        #pragma unroll
        for (int c = 0; c < 2; c++) {
            int ch = cb + c;
            CPA(dB + (((ch ^ (row & 7))) << 4), sp + ch * 16);
        }
    }
}

__global__ __launch_bounds__(256, 2) void gemm_kernel() {
    extern __shared__ char smem[];
    const int tid = threadIdx.x;
    const int wid = tid >> 5;
    const int lane = tid & 31;

    // decode tile: tj >= 2*ti, count per ti = 32 - 2*ti
    int ti = 0, r = blockIdx.x, c = 32;
    while (r >= c) { r -= c; c -= 2; ti++; }
    const int tj = 2 * ti + r;
    const int bi = ti * TM;
    const int bj = tj * TN;
    const bool band = (r < 2);              // tile intersects its own row band

    const int mloc = (wid >> 1) * 32;       // 4 m-warps of 32 rows
    const int nloc = (wid & 1) * 32;        // 2 n-warps of 32 cols
    const uint32_t smb = smem_to_u32(smem);
    float* sSqi = reinterpret_cast<float*>(smem + SM_SQI);
    float* sSqj = reinterpret_cast<float*>(smem + SM_SQJ);

    load_slab_async(smb, 0, 0, bi, bj, tid);
    CPA_COMMIT();

    if (tid < 128) sSqi[tid] = g_sq[bi + tid];
    else if (tid < 192) sSqj[tid - 128] = g_sq[bj + (tid - 128)];

    float acc[2][4][4];
    #pragma unroll
    for (int mi = 0; mi < 2; mi++)
        #pragma unroll
        for (int ni = 0; ni < 4; ni++)
            #pragma unroll
            for (int rr = 0; rr < 4; rr++) acc[mi][ni][rr] = 0.0f;

    const int rA = (lane & 7) + (((lane >> 3) & 1) << 3);
    const int cSel = lane >> 4;
    const int x7 = lane & 7;
    uint32_t koff[4];
    #pragma unroll
    for (int ks = 0; ks < 4; ks++) koff[ks] = ((uint32_t)((2 * ks + cSel) ^ x7)) << 4;
    const uint32_t arow = (uint32_t)(mloc + rA) * 128;
    const uint32_t brow = (uint32_t)(nloc + rA) * 128;

    #pragma unroll 1
    for (int s = 0; s < NSLAB; s++) {
        const int b = s & 1;
        if (s + 1 < NSLAB) { load_slab_async(smb, 1 - b, s + 1, bi, bj, tid); CPA_COMMIT(); }
        if (s + 1 < NSLAB) asm volatile("cp.async.wait_group 1;" ::: "memory");
        else               asm volatile("cp.async.wait_group 0;" ::: "memory");
        __syncthreads();

        const uint32_t base = smb + SM_BUF + b * BUFSZ;
        const uint32_t baseA = base + A_OFF + arow;
        const uint32_t baseB = base + B_OFF + brow;
        #pragma unroll
        for (int ks = 0; ks < 4; ks++) {
            uint32_t af[2][4];
            ldm_x4(af[0], baseA + koff[ks]);
            ldm_x4(af[1], baseA + 16 * 128 + koff[ks]);
            uint32_t bfr[2][4];
            ldm_x4(bfr[0], baseB + koff[ks]);
            ldm_x4(bfr[1], baseB + 16 * 128 + koff[ks]);
            #pragma unroll
            for (int mi = 0; mi < 2; mi++)
                #pragma unroll
                for (int nt = 0; nt < 2; nt++) {
                    mma_fp16(acc[mi][2 * nt],     af[mi], bfr[nt][0], bfr[nt][2]);
                    mma_fp16(acc[mi][2 * nt + 1], af[mi], bfr[nt][1], bfr[nt][3]);
                }
        }
        __syncthreads();
    }

    // normal-orientation store: d = sqi + sqj - 2*dot
    #pragma unroll
    for (int mi = 0; mi < 2; mi++) {
        #pragma unroll
        for (int h = 0; h < 2; h++) {
            const int rl = mloc + mi * 16 + h * 8 + (lane >> 2);
            const float sqi = sSqi[rl];
            float* drow = g_dist + (size_t)(bi + rl) * NN + bj;
            #pragma unroll
            for (int ni = 0; ni < 4; ni++) {
                const int cl = nloc + ni * 8 + (lane & 3) * 2;
                float2 o;
                o.x = fmaf(-2.0f, acc[mi][ni][h * 2 + 0], sqi + sSqj[cl]);
                o.y = fmaf(-2.0f, acc[mi][ni][h * 2 + 1], sqi + sSqj[cl + 1]);
                *reinterpret_cast<float2*>(drow + cl) = o;
            }
        }
    }

    // transposed copy for off-band tiles, staged through smem for coalescing
    if (!band) {
        float* sT = reinterpret_cast<float*>(smem + SM_BUF);  // 64 x 132
        __syncthreads();   // mainloop buffers fully consumed above
        #pragma unroll
        for (int mi = 0; mi < 2; mi++) {
            #pragma unroll
            for (int h = 0; h < 2; h++) {
                const int rl = mloc + mi * 16 + h * 8 + (lane >> 2);
                const float sqi = sSqi[rl];
                #pragma unroll
                for (int ni = 0; ni < 4; ni++) {
                    const int cl = nloc + ni * 8 + (lane & 3) * 2;
                    sT[(cl + 0) * TSTRIDE + rl] = fmaf(-2.0f, acc[mi][ni][h * 2 + 0], sqi + sSqj[cl]);
                    sT[(cl + 1) * TSTRIDE + rl] = fmaf(-2.0f, acc[mi][ni][h * 2 + 1], sqi + sSqj[cl + 1]);
                }
            }
        }
        __syncthreads();
        const int cc = tid >> 2, part = tid & 3;   // 4 threads per col-row, 64 rows
        float* dout = g_dist + (size_t)(bj + cc) * NN + bi + part * 32;
        const float* srow = sT + cc * TSTRIDE + part * 32;
        #pragma unroll
        for (int i = 0; i < 8; i++)
            reinterpret_cast<float4*>(dout)[i] = reinterpret_cast<const float4*>(srow)[i];
    }
}

// ---------------------------------------------------------------------------
// 3) triplet_kernel: one CTA per row; positives read from g_dist;
//    loads hoisted above preamble; no atomics; fused last-block finalize
// ---------------------------------------------------------------------------
__global__ __launch_bounds__(256) void triplet_kernel(float* __restrict__ out, int out_size) {
    const int row = blockIdx.x;
    const int cls = row >> 3;
    const int tid = threadIdx.x;
    const float L2E = 1.4426950408889634f;
    const float LN2 = 0.6931471805599453f;

    const float* drow = g_dist + (size_t)row * NN;

    // hoisted loads (overlap preamble latency)
    const float4 dva = *reinterpret_cast<const float4*>(drow + tid * 4);
    const float4 dvb = *reinterpret_cast<const float4*>(drow + 1024 + tid * 4);

    // positives preamble: 8 intra-class dists from this row
    __shared__ float sP[8], sT[8];
    if (tid < 8) {
        const int j = cls * KPC + tid;
        const float p = drow[j];
        const bool self = (j == row);
        sP[tid] = self ? 0.0f : fast_exp2(p * L2E);
        sT[tid] = self ? -1.0e30f : (p + 2.9447e-4f);
        float ps = self ? 0.0f : p;
        ps += __shfl_xor_sync(0x000000ffu, ps, 1);
        ps += __shfl_xor_sync(0x000000ffu, ps, 2);
        ps += __shfl_xor_sync(0x000000ffu, ps, 4);
        if (tid == 0) g_row[row * 4 + 2] = ps;
    }
    __syncthreads();
    const float4 p0 = *reinterpret_cast<const float4*>(sP);
    const float4 p1 = *reinterpret_cast<const float4*>(sP + 4);
    const float4 t0 = *reinterpret_cast<const float4*>(sT);
    const float4 t1 = *reinterpret_cast<const float4*>(sT + 4);

    int ic = 0;
    float tr = 0.0f, ng = 0.0f;

    #pragma unroll
    for (int half = 0; half < 2; half++) {
        const int j0 = half * 1024 + tid * 4;
        const float4 dv = half ? dvb : dva;
        const float dd[4] = { dv.x, dv.y, dv.z, dv.w };
        #pragma unroll
        for (int q = 0; q < 4; q++) {
            const int j = j0 + q;
            if ((j >> 3) == cls) continue;
            const float d = dd[q];
            ng += d;
            const float en = fast_exp2(-d * L2E);
            const bool v0 = d < t0.x, v1 = d < t0.y, v2 = d < t0.z, v3 = d < t0.w;
            const bool v4 = d < t1.x, v5 = d < t1.y, v6 = d < t1.z, v7 = d < t1.w;
            ic += (int)v0 + (int)v1 + (int)v2 + (int)v3
                + (int)v4 + (int)v5 + (int)v6 + (int)v7;
            float a0 = (v0 ? fmaf(p0.x, en, 1.0f) : 1.0f) * (v1 ? fmaf(p0.y, en, 1.0f) : 1.0f);
            float a1 = (v2 ? fmaf(p0.z, en, 1.0f) : 1.0f) * (v3 ? fmaf(p0.w, en, 1.0f) : 1.0f);
            float b0 = (v4 ? fmaf(p1.x, en, 1.0f) : 1.0f) * (v5 ? fmaf(p1.y, en, 1.0f) : 1.0f);
            float b1 = (v6 ? fmaf(p1.z, en, 1.0f) : 1.0f) * (v7 ? fmaf(p1.w, en, 1.0f) : 1.0f);
            tr += fast_log2(a0 * a1) + fast_log2(b0 * b1);
        }
    }

    float cnt = (float)ic;
    float trip = LN2 * tr;
    cnt  = warp_sum(cnt);
    trip = warp_sum(trip);
    ng   = warp_sum(ng);
    __shared__ float r0[8], r1[8], r2[8];
    const int w = tid >> 5;
    if ((tid & 31) == 0) { r0[w] = cnt; r1[w] = trip; r2[w] = ng; }
    __syncthreads();
    if (tid == 0) {
        float cs = 0, ts = 0, ns = 0;
        #pragma unroll
        for (int ww = 0; ww < 8; ww++) { cs += r0[ww]; ts += r1[ww]; ns += r2[ww]; }
        g_row[row * 4 + 0] = cs;
        g_row[row * 4 + 1] = ts;
        g_row[row * 4 + 3] = ns;
    }

    // ---- last-block finalize ----
    __syncthreads();
    __shared__ int slast;
    if (tid == 0) {
        __threadfence();
        int o = atomicAdd(&g_done, 1);
        slast = (o == NN - 1);
    }
    __syncthreads();
    if (!slast) return;
    __threadfence();

    double sm = 0, tc = 0, acd = 0, psd = 0, nsd = 0;
    for (int i = tid; i < NN; i += 256) {
        float4 rr = *reinterpret_cast<const float4*>(g_row + i * 4);
        tc += (double)rr.x; psd += (double)rr.z; nsd += (double)rr.w;
        if (rr.x > 0.0f) sm += (double)(rr.y / rr.x);
        else             acd += 1.0;
    }
    #pragma unroll
    for (int o = 16; o; o >>= 1) {
        sm  += __shfl_xor_sync(0xffffffffu, sm, o);
        tc  += __shfl_xor_sync(0xffffffffu, tc, o);
        acd += __shfl_xor_sync(0xffffffffu, acd, o);
        psd += __shfl_xor_sync(0xffffffffu, psd, o);
        nsd += __shfl_xor_sync(0xffffffffu, nsd, o);
    }
    __shared__ double sh[5][8];
    if ((tid & 31) == 0) { sh[0][w] = sm; sh[1][w] = tc; sh[2][w] = acd; sh[3][w] = psd; sh[4][w] = nsd; }
    __syncthreads();
    if (tid == 0) {
        double Sm = 0, Tc = 0, Ac = 0, Ps = 0, Ns = 0;
        #pragma unroll
        for (int ww = 0; ww < 8; ww++) {
            Sm += sh[0][ww]; Tc += sh[1][ww]; Ac += sh[2][ww]; Ps += sh[3][ww]; Ns += sh[4][ww];
        }
        float loss = (Tc > 0.0) ? (float)(Sm / Tc) : 0.0f;
        if (out_size >= 1) out[0] = loss;
        if (out_size >= 2) out[1] = (float)(Ac / (double)NN);
        if (out_size >= 3) out[2] = (float)(Ps / ((double)NN * (KPC - 1)));
        if (out_size >= 4) out[3] = (float)(Ns / ((double)NN * (NN - KPC)));
    }
    for (int idx = 4 + tid; idx < out_size; idx += 256) out[idx] = 0.0f;
}

// ---------------------------------------------------------------------------
extern "C" void kernel_launch(void* const* d_in, const int* in_sizes, int n_in,
                              void* d_out, int out_size) {
    const float* inputs = (const float*)d_in[0];
    (void)in_sizes; (void)n_in;
    float* out = (float*)d_out;

    cudaFuncSetAttribute(gemm_kernel, cudaFuncAttributeMaxDynamicSharedMemorySize, SMEM_TOTAL);
    cudaFuncSetAttribute(gemm_kernel, cudaFuncAttributePreferredSharedMemoryCarveout, 100);

    prep_kernel<<<NN / 8, 256>>>(inputs);
    gemm_kernel<<<NGEMM, 256, SMEM_TOTAL>>>();
    triplet_kernel<<<NN, 256>>>(out, out_size);
}

// round 15
// speedup vs baseline: 1.0506x; 1.0506x over previous
#include <cuda_runtime.h>
#include <cuda_fp16.h>
#include <cstdint>

#define NN 2048
#define DD 512
#define KPC 8
#define TM 128
#define TN 128
#define KS 64
#define NSLAB (DD / KS)
#define NGEMM 136          // 16*17/2 upper-triangular tiles
#define RPC 2              // rows per triplet CTA

// ---------------- scratch (no allocations allowed) ----------------
__device__ __half g_xf[NN * DD];             // fp16 normalized (MMA operand)
__device__ float g_sq[NN];
__device__ float g_dist[(size_t)NN * NN];    // 16 MB distance matrix
__device__ float g_row[NN * 4];              // cnt, trip_sum, pos_sum, neg_sum
__device__ int g_done;

// ---------------- helpers ----------------
__device__ __forceinline__ uint32_t smem_to_u32(const void* p) {
    uint32_t a;
    asm("{ .reg .u64 t; cvta.to.shared.u64 t, %1; cvt.u32.u64 %0, t; }" : "=r"(a) : "l"(p));
    return a;
}
__device__ __forceinline__ float fast_exp2(float x) { float y; asm("ex2.approx.f32 %0, %1;" : "=f"(y) : "f"(x)); return y; }
__device__ __forceinline__ float fast_log2(float x) { float y; asm("lg2.approx.f32 %0, %1;" : "=f"(y) : "f"(x)); return y; }
__device__ __forceinline__ float warp_sum(float v) {
    #pragma unroll
    for (int o = 16; o; o >>= 1) v += __shfl_xor_sync(0xffffffffu, v, o);
    return v;
}

#define CPA(dst, src) \
    asm volatile("cp.async.cg.shared.global [%0], [%1], 16;" :: "r"(dst), "l"(src))
#define CPA_COMMIT() asm volatile("cp.async.commit_group;" ::: "memory")

__device__ __forceinline__ void ldm_x4(uint32_t* r, uint32_t addr) {
    asm volatile("ldmatrix.sync.aligned.m8n8.x4.shared.b16 {%0,%1,%2,%3}, [%4];"
                 : "=r"(r[0]), "=r"(r[1]), "=r"(r[2]), "=r"(r[3]) : "r"(addr));
}
__device__ __forceinline__ void mma_fp16(float* c, const uint32_t* a, uint32_t b0, uint32_t b1) {
    asm volatile(
        "mma.sync.aligned.m16n8k16.row.col.f32.f16.f16.f32 "
        "{%0,%1,%2,%3}, {%4,%5,%6,%7}, {%8,%9}, {%0,%1,%2,%3};"
        : "+f"(c[0]), "+f"(c[1]), "+f"(c[2]), "+f"(c[3])
        : "r"(a[0]), "r"(a[1]), "r"(a[2]), "r"(a[3]), "r"(b0), "r"(b1));
}

// ---------------------------------------------------------------------------
// 1) prep: normalize + fp16 + sq only (positives come from g_dist later)
// ---------------------------------------------------------------------------
__global__ __launch_bounds__(256) void prep_kernel(const float* __restrict__ in) {
    const int tid = threadIdx.x;
    const int w = tid >> 5;
    const int l = tid & 31;
    const int row = blockIdx.x * 8 + w;
    if (blockIdx.x == 0 && tid == 0) g_done = 0;

    float4 v[4];
    const float4* src = reinterpret_cast<const float4*>(in + row * DD) + l * 4;
    #pragma unroll
    for (int q = 0; q < 4; q++) v[q] = src[q];
    float ss = 0.0f;
    #pragma unroll
    for (int q = 0; q < 4; q++)
        ss += v[q].x * v[q].x + v[q].y * v[q].y + v[q].z * v[q].z + v[q].w * v[q].w;
    ss = warp_sum(ss);
    float s = 4.0f * rsqrtf(ss);

    __half2* pf = reinterpret_cast<__half2*>(g_xf + row * DD + l * 16);
    #pragma unroll
    for (int q = 0; q < 4; q++) {
        pf[q * 2 + 0] = __half2(__float2half_rn(v[q].x * s), __float2half_rn(v[q].y * s));
        pf[q * 2 + 1] = __half2(__float2half_rn(v[q].z * s), __float2half_rn(v[q].w * s));
    }
    if (l == 0) g_sq[row] = ss * s * s;
}

// ---------------------------------------------------------------------------
// 2) gemm_kernel: symmetric HMMA Gram, 136 upper-tri 128x128 tiles (R13 winner)
// ---------------------------------------------------------------------------
#define SM_SQI 0
#define SM_SQJ 512
#define SM_BUF 1024
#define A_OFF 0
#define B_OFF 16384
#define BUFSZ 32768
#define TSTRIDE 132
#define SMEM_TOTAL (SM_BUF + TM * TSTRIDE * 4)   // 68608 > mainloop's 66560

__device__ __forceinline__ void load_slab_async(uint32_t smb, int buf, int s,
                                                int bi, int bj, int tid) {
    const int k0 = s * KS;
    const uint32_t bufb = smb + SM_BUF + buf * BUFSZ;
    const int row = tid >> 1;
    const int cb = (tid & 1) * 4;
    {
        const char* sp = reinterpret_cast<const char*>(g_xf + (bi + row) * DD + k0);
        uint32_t dA = bufb + A_OFF + row * 128;
        #pragma unroll
        for (int c = 0; c < 4; c++) {
            int ch = cb + c;
            CPA(dA + (((ch ^ (row & 7))) << 4), sp + ch * 16);
        }
    }
    {
        const char* sp = reinterpret_cast<const char*>(g_xf + (bj + row) * DD + k0);
        uint32_t dB = bufb + B_OFF + row * 128;
        #pragma unroll
        for (int c = 0; c < 4; c++) {
            int ch = cb + c;
            CPA(dB + (((ch ^ (row & 7))) << 4), sp + ch * 16);
        }
    }
}

__global__ __launch_bounds__(256, 2) void gemm_kernel() {
    extern __shared__ char smem[];
    const int tid = threadIdx.x;
    const int wid = tid >> 5;
    const int lane = tid & 31;

    // decode upper-triangular tile (ti <= tj)
    int ti = 0, r = blockIdx.x, c = 16;
    while (r >= c) { r -= c; c--; ti++; }
    const int tj = ti + r;
    const int bi = ti * TM;
    const int bj = tj * TN;

    const int mloc = (wid >> 2) * 64;
    const int nloc = (wid & 3) * 32;
    const uint32_t smb = smem_to_u32(smem);
    float* sSqi = reinterpret_cast<float*>(smem + SM_SQI);
    float* sSqj = reinterpret_cast<float*>(smem + SM_SQJ);

    load_slab_async(smb, 0, 0, bi, bj, tid);
    CPA_COMMIT();

    if (tid < 128) sSqi[tid] = g_sq[bi + tid];
    else           sSqj[tid - 128] = g_sq[bj + (tid - 128)];

    float acc[4][4][4];
    #pragma unroll
    for (int mi = 0; mi < 4; mi++)
        #pragma unroll
        for (int ni = 0; ni < 4; ni++)
            #pragma unroll
            for (int rr = 0; rr < 4; rr++) acc[mi][ni][rr] = 0.0f;

    const int rA = (lane & 7) + (((lane >> 3) & 1) << 3);
    const int cSel = lane >> 4;
    const int x7 = lane & 7;
    uint32_t koff[4];
    #pragma unroll
    for (int ks = 0; ks < 4; ks++) koff[ks] = ((uint32_t)((2 * ks + cSel) ^ x7)) << 4;
    const uint32_t arow = (uint32_t)(mloc + rA) * 128;
    const uint32_t brow = (uint32_t)(nloc + rA) * 128;

    #pragma unroll 1
    for (int s = 0; s < NSLAB; s++) {
        const int b = s & 1;
        if (s + 1 < NSLAB) { load_slab_async(smb, 1 - b, s + 1, bi, bj, tid); CPA_COMMIT(); }
        if (s + 1 < NSLAB) asm volatile("cp.async.wait_group 1;" ::: "memory");
        else               asm volatile("cp.async.wait_group 0;" ::: "memory");
        __syncthreads();

        const uint32_t base = smb + SM_BUF + b * BUFSZ;
        const uint32_t baseA = base + A_OFF + arow;
        const uint32_t baseB = base + B_OFF + brow;
        #pragma unroll
        for (int ks = 0; ks < 4; ks++) {
            uint32_t af[4][4];
            #pragma unroll
            for (int mi = 0; mi < 4; mi++) ldm_x4(af[mi], baseA + mi * (16 * 128) + koff[ks]);
            uint32_t bfr[2][4];
            #pragma unroll
            for (int nt = 0; nt < 2; nt++) ldm_x4(bfr[nt], baseB + nt * (16 * 128) + koff[ks]);
            #pragma unroll
            for (int mi = 0; mi < 4; mi++)
                #pragma unroll
                for (int nt = 0; nt < 2; nt++) {
                    mma_fp16(acc[mi][2 * nt],     af[mi], bfr[nt][0], bfr[nt][2]);
                    mma_fp16(acc[mi][2 * nt + 1], af[mi], bfr[nt][1], bfr[nt][3]);
                }
        }
        __syncthreads();
    }

    // normal-orientation store: d = sqi + sqj - 2*dot
    #pragma unroll
    for (int mi = 0; mi < 4; mi++) {
        #pragma unroll
        for (int h = 0; h < 2; h++) {
            const int rl = mloc + mi * 16 + h * 8 + (lane >> 2);
            const float sqi = sSqi[rl];
            float* drow = g_dist + (size_t)(bi + rl) * NN + bj;
            #pragma unroll
            for (int ni = 0; ni < 4; ni++) {
                const int cl = nloc + ni * 8 + (lane & 3) * 2;
                float2 o;
                o.x = fmaf(-2.0f, acc[mi][ni][h * 2 + 0], sqi + sSqj[cl]);
                o.y = fmaf(-2.0f, acc[mi][ni][h * 2 + 1], sqi + sSqj[cl + 1]);
                *reinterpret_cast<float2*>(drow + cl) = o;
            }
        }
    }

    // transposed copy for off-diagonal tiles, staged through smem for coalescing
    if (ti != tj) {
        float* sT = reinterpret_cast<float*>(smem + SM_BUF);  // 128 x 132
        #pragma unroll
        for (int mi = 0; mi < 4; mi++) {
            #pragma unroll
            for (int h = 0; h < 2; h++) {
                const int rl = mloc + mi * 16 + h * 8 + (lane >> 2);
                const float sqi = sSqi[rl];
                #pragma unroll
                for (int ni = 0; ni < 4; ni++) {
                    const int cl = nloc + ni * 8 + (lane & 3) * 2;
                    sT[(cl + 0) * TSTRIDE + rl] = fmaf(-2.0f, acc[mi][ni][h * 2 + 0], sqi + sSqj[cl]);
                    sT[(cl + 1) * TSTRIDE + rl] = fmaf(-2.0f, acc[mi][ni][h * 2 + 1], sqi + sSqj[cl + 1]);
                }
            }
        }
        __syncthreads();
        const int cc = tid >> 1, hf = tid & 1;
        float* dout = g_dist + (size_t)(bj + cc) * NN + bi + hf * 64;
        const float* srow = sT + cc * TSTRIDE + hf * 64;
        #pragma unroll
        for (int i = 0; i < 16; i++)
            reinterpret_cast<float4*>(dout)[i] = reinterpret_cast<const float4*>(srow)[i];
    }
}

// ---------------------------------------------------------------------------
// 3) triplet_kernel: 2 rows per CTA (same class), 4 front-loaded LDG.128,
//    two independent accumulator chains; fused last-block finalize
// ---------------------------------------------------------------------------
__global__ __launch_bounds__(256) void triplet_kernel(float* __restrict__ out, int out_size) {
    const int row0 = blockIdx.x * RPC;
    const int cls = row0 >> 3;          // rows 2b,2b+1 share the class
    const int tid = threadIdx.x;
    const float L2E = 1.4426950408889634f;
    const float LN2 = 0.6931471805599453f;

    const float* dr0 = g_dist + (size_t)row0 * NN;
    const float* dr1 = dr0 + NN;

    // front-load 4 independent LDG.128
    const float4 a0 = *reinterpret_cast<const float4*>(dr0 + tid * 4);
    const float4 b0 = *reinterpret_cast<const float4*>(dr0 + 1024 + tid * 4);
    const float4 a1 = *reinterpret_cast<const float4*>(dr1 + tid * 4);
    const float4 b1 = *reinterpret_cast<const float4*>(dr1 + 1024 + tid * 4);

    // positives preamble: warp 0 lanes 0-7 -> row0, warp 1 lanes 0-7 -> row1
    __shared__ float sP[RPC][8], sT[RPC][8];
    const int w = tid >> 5;
    const int l = tid & 31;
    if (w < RPC && l < 8) {
        const int row = row0 + w;
        const float p = (w ? dr1 : dr0)[cls * KPC + l];
        const bool self = (cls * KPC + l) == row;
        sP[w][l] = self ? 0.0f : fast_exp2(p * L2E);
        sT[w][l] = self ? -1.0e30f : (p + 2.9447e-4f);
        float ps = self ? 0.0f : p;
        ps += __shfl_xor_sync(0x000000ffu, ps, 1);
        ps += __shfl_xor_sync(0x000000ffu, ps, 2);
        ps += __shfl_xor_sync(0x000000ffu, ps, 4);
        if (l == 0) g_row[row * 4 + 2] = ps;
    }
    __syncthreads();
    const float4 P00 = *reinterpret_cast<const float4*>(&sP[0][0]);
    const float4 P01 = *reinterpret_cast<const float4*>(&sP[0][4]);
    const float4 T00 = *reinterpret_cast<const float4*>(&sT[0][0]);
    const float4 T01 = *reinterpret_cast<const float4*>(&sT[0][4]);
    const float4 P10 = *reinterpret_cast<const float4*>(&sP[1][0]);
    const float4 P11 = *reinterpret_cast<const float4*>(&sP[1][4]);
    const float4 T10 = *reinterpret_cast<const float4*>(&sT[1][0]);
    const float4 T11 = *reinterpret_cast<const float4*>(&sT[1][4]);

    int ic0 = 0, ic1 = 0;
    float tr0 = 0.0f, tr1 = 0.0f, ng0 = 0.0f, ng1 = 0.0f;

    #pragma unroll
    for (int half = 0; half < 2; half++) {
        const int j0 = half * 1024 + tid * 4;
        const float4 d0v = half ? b0 : a0;
        const float4 d1v = half ? b1 : a1;
        const float dd0[4] = { d0v.x, d0v.y, d0v.z, d0v.w };
        const float dd1[4] = { d1v.x, d1v.y, d1v.z, d1v.w };
        #pragma unroll
        for (int q = 0; q < 4; q++) {
            const int j = j0 + q;
            if ((j >> 3) == cls) continue;
            // row 0
            {
                const float d = dd0[q];
                ng0 += d;
                const float en = fast_exp2(-d * L2E);
                const bool v0 = d < T00.x, v1 = d < T00.y, v2 = d < T00.z, v3 = d < T00.w;
                const bool v4 = d < T01.x, v5 = d < T01.y, v6 = d < T01.z, v7 = d < T01.w;
                ic0 += (int)v0 + (int)v1 + (int)v2 + (int)v3
                     + (int)v4 + (int)v5 + (int)v6 + (int)v7;
                float x0 = (v0 ? fmaf(P00.x, en, 1.0f) : 1.0f) * (v1 ? fmaf(P00.y, en, 1.0f) : 1.0f);
                float x1 = (v2 ? fmaf(P00.z, en, 1.0f) : 1.0f) * (v3 ? fmaf(P00.w, en, 1.0f) : 1.0f);
                float y0 = (v4 ? fmaf(P01.x, en, 1.0f) : 1.0f) * (v5 ? fmaf(P01.y, en, 1.0f) : 1.0f);
                float y1 = (v6 ? fmaf(P01.z, en, 1.0f) : 1.0f) * (v7 ? fmaf(P01.w, en, 1.0f) : 1.0f);
                tr0 += fast_log2(x0 * x1) + fast_log2(y0 * y1);
            }
            // row 1 (independent chain)
            {
                const float d = dd1[q];
                ng1 += d;
                const float en = fast_exp2(-d * L2E);
                const bool v0 = d < T10.x, v1 = d < T10.y, v2 = d < T10.z, v3 = d < T10.w;
                const bool v4 = d < T11.x, v5 = d < T11.y, v6 = d < T11.z, v7 = d < T11.w;
                ic1 += (int)v0 + (int)v1 + (int)v2 + (int)v3
                     + (int)v4 + (int)v5 + (int)v6 + (int)v7;
                float x0 = (v0 ? fmaf(P10.x, en, 1.0f) : 1.0f) * (v1 ? fmaf(P10.y, en, 1.0f) : 1.0f);
                float x1 = (v2 ? fmaf(P10.z, en, 1.0f) : 1.0f) * (v3 ? fmaf(P10.w, en, 1.0f) : 1.0f);
                float y0 = (v4 ? fmaf(P11.x, en, 1.0f) : 1.0f) * (v5 ? fmaf(P11.y, en, 1.0f) : 1.0f);
                float y1 = (v6 ? fmaf(P11.z, en, 1.0f) : 1.0f) * (v7 ? fmaf(P11.w, en, 1.0f) : 1.0f);
                tr1 += fast_log2(x0 * x1) + fast_log2(y0 * y1);
            }
        }
    }

    float c0 = warp_sum((float)ic0);
    float t0 = warp_sum(LN2 * tr0);
    float n0 = warp_sum(ng0);
    float c1 = warp_sum((float)ic1);
    float t1 = warp_sum(LN2 * tr1);
    float n1 = warp_sum(ng1);
    __shared__ float red[6][8];
    if (l == 0) {
        red[0][w] = c0; red[1][w] = t0; red[2][w] = n0;
        red[3][w] = c1; red[4][w] = t1; red[5][w] = n1;
    }
    __syncthreads();
    if (tid < 2) {
        float cs = 0, ts = 0, ns = 0;
        #pragma unroll
        for (int ww = 0; ww < 8; ww++) {
            cs += red[tid * 3 + 0][ww];
            ts += red[tid * 3 + 1][ww];
            ns += red[tid * 3 + 2][ww];
        }
        const int row = row0 + tid;
        g_row[row * 4 + 0] = cs;
        g_row[row * 4 + 1] = ts;
        g_row[row * 4 + 3] = ns;
    }

    // ---- last-block finalize ----
    __syncthreads();
    __shared__ int slast;
    if (tid == 0) {
        __threadfence();
        int o = atomicAdd(&g_done, 1);
        slast = (o == NN / RPC - 1);
    }
    __syncthreads();
    if (!slast) return;
    __threadfence();

    double sm = 0, tc = 0, acd = 0, psd = 0, nsd = 0;
    for (int i = tid; i < NN; i += 256) {
        float4 rr = *reinterpret_cast<const float4*>(g_row + i * 4);
        tc += (double)rr.x; psd += (double)rr.z; nsd += (double)rr.w;
        if (rr.x > 0.0f) sm += (double)(rr.y / rr.x);
        else             acd += 1.0;
    }
    #pragma unroll
    for (int o = 16; o; o >>= 1) {
        sm  += __shfl_xor_sync(0xffffffffu, sm, o);
        tc  += __shfl_xor_sync(0xffffffffu, tc, o);
        acd += __shfl_xor_sync(0xffffffffu, acd, o);
        psd += __shfl_xor_sync(0xffffffffu, psd, o);
        nsd += __shfl_xor_sync(0xffffffffu, nsd, o);
    }
    __shared__ double sh[5][8];
    if (l == 0) { sh[0][w] = sm; sh[1][w] = tc; sh[2][w] = acd; sh[3][w] = psd; sh[4][w] = nsd; }
    __syncthreads();
    if (tid == 0) {
        double Sm = 0, Tc = 0, Ac = 0, Ps = 0, Ns = 0;
        #pragma unroll
        for (int ww = 0; ww < 8; ww++) {
            Sm += sh[0][ww]; Tc += sh[1][ww]; Ac += sh[2][ww]; Ps += sh[3][ww]; Ns += sh[4][ww];
        }
        float loss = (Tc > 0.0) ? (float)(Sm / Tc) : 0.0f;
        if (out_size >= 1) out[0] = loss;
        if (out_size >= 2) out[1] = (float)(Ac / (double)NN);
        if (out_size >= 3) out[2] = (float)(Ps / ((double)NN * (KPC - 1)));
        if (out_size >= 4) out[3] = (float)(Ns / ((double)NN * (NN - KPC)));
    }
    for (int idx = 4 + tid; idx < out_size; idx += 256) out[idx] = 0.0f;
}

// ---------------------------------------------------------------------------
extern "C" void kernel_launch(void* const* d_in, const int* in_sizes, int n_in,
                              void* d_out, int out_size) {
    const float* inputs = (const float*)d_in[0];
    (void)in_sizes; (void)n_in;
    float* out = (float*)d_out;

    cudaFuncSetAttribute(gemm_kernel, cudaFuncAttributeMaxDynamicSharedMemorySize, SMEM_TOTAL);
    cudaFuncSetAttribute(gemm_kernel, cudaFuncAttributePreferredSharedMemoryCarveout, 100);

    prep_kernel<<<NN / 8, 256>>>(inputs);
    gemm_kernel<<<NGEMM, 256, SMEM_TOTAL>>>();
    triplet_kernel<<<NN / RPC, 256>>>(out, out_size);
}